// round 14
// baseline (speedup 1.0000x reference)
#include <cuda_runtime.h>
#include <cuda_bf16.h>
#include <math_constants.h>

// Banded sparse attention: B=256, S=128, DM=1024, H=16, Dh=64, half-width W=4.
// Grid (H, 2, B): each block owns 64 consecutive queries of one (b,h) tile.
// 128 threads, NO shared memory. 8-lane group owns 4 adjacent queries; lane
// `ds` owns dim chunks {ds, ds+8} (16B each) -> every K/V/Q/out instruction
// covers contiguous 128B per group (4 L1 wavefronts/warp-instruction).
// __launch_bounds__(128, 6): cap regs at 84 so 6 blocks/SM (24 warps) fit ->
// more outstanding DRAM loads; kernel is latency-limited at the HBM roofline.

namespace {
constexpr int S   = 128;
constexpr int DM  = 1024;
constexpr int H   = 16;
constexpr int W   = 4;
constexpr int QPT = 4;              // queries per 8-lane group
constexpr int NR  = 2 * W + QPT;    // 12 band-union rows per group
constexpr float SCALE = 0.125f;
constexpr int THREADS = 128;        // 4 warps = 16 groups = 64 queries/block
}  // namespace

__device__ __forceinline__ int clampr(int r) { return min(max(r, 0), S - 1); }

__global__ __launch_bounds__(THREADS, 6)
void banded_attn_kernel(const float* __restrict__ q,
                        const float* __restrict__ k,
                        const float* __restrict__ v,
                        float* __restrict__ out) {
    const int h    = blockIdx.x;
    const int half = blockIdx.y;     // which 64-query half of the tile
    const int b    = blockIdx.z;
    const int tid  = threadIdx.x;
    const int lane = tid & 31;
    const int warp = tid >> 5;

    const int ds  = lane & 7;                          // dim slice 0..7
    const int grp = warp * 4 + (lane >> 3);            // group 0..15
    const int r0  = half * 64 + grp * QPT;             // first query of group

    const size_t gbase = (size_t)b * S * DM + (size_t)h * 64;

    // ---- Scores ----
    // On owner lane ds==qi (qi<4): s[jj] = score of query r0+qi vs row r0-W+jj.
    float s[NR];
    #pragma unroll
    for (int jj = 0; jj < NR; ++jj) s[jj] = 0.0f;

    {
        // This lane's slices of the 4 Q rows (chunks ds and ds+8)
        float4 qr[QPT][2];
        #pragma unroll
        for (int qi = 0; qi < QPT; ++qi) {
            const float* qrow = q + gbase + (size_t)(r0 + qi) * DM;
            qr[qi][0] = *reinterpret_cast<const float4*>(qrow + ds * 4);
            qr[qi][1] = *reinterpret_cast<const float4*>(qrow + 32 + ds * 4);
        }

        #pragma unroll
        for (int jj = 0; jj < NR; ++jj) {
            const float* krow = k + gbase + (size_t)clampr(r0 - W + jj) * DM;
            const float4 k0 = *reinterpret_cast<const float4*>(krow + ds * 4);
            const float4 k1 = *reinterpret_cast<const float4*>(krow + 32 + ds * 4);
            #pragma unroll
            for (int qi = 0; qi < QPT; ++qi) {
                if (jj >= qi && jj <= qi + 2 * W) {       // live (qi,jj) only
                    float p = 0.0f;
                    p = fmaf(qr[qi][0].x, k0.x, p); p = fmaf(qr[qi][0].y, k0.y, p);
                    p = fmaf(qr[qi][0].z, k0.z, p); p = fmaf(qr[qi][0].w, k0.w, p);
                    p = fmaf(qr[qi][1].x, k1.x, p); p = fmaf(qr[qi][1].y, k1.y, p);
                    p = fmaf(qr[qi][1].z, k1.z, p); p = fmaf(qr[qi][1].w, k1.w, p);
                    // reduce over the 8 dim-slices of this group
                    p += __shfl_xor_sync(0xffffffffu, p, 1);
                    p += __shfl_xor_sync(0xffffffffu, p, 2);
                    p += __shfl_xor_sync(0xffffffffu, p, 4);
                    if (ds == qi) s[jj] = p;              // owner lane keeps it
                }
            }
        }
    }

    // ---- Softmax (owner lanes ds<4; query r0+ds, live jj in [ds, ds+2W]) ----
    {
        float m = -CUDART_INF_F;
        #pragma unroll
        for (int jj = 0; jj < NR; ++jj) {
            const int r = r0 - W + jj;
            const bool live = (jj >= ds) && (jj <= ds + 2 * W) && (r >= 0) && (r < S);
            s[jj] = live ? s[jj] * SCALE : -CUDART_INF_F;
            m = fmaxf(m, s[jj]);
        }
        float sum = 0.0f;
        #pragma unroll
        for (int jj = 0; jj < NR; ++jj) { s[jj] = __expf(s[jj] - m); sum += s[jj]; }
        const float inv = 1.0f / sum;
        #pragma unroll
        for (int jj = 0; jj < NR; ++jj) s[jj] *= inv;     // masked slots -> 0
    }

    // ---- Output: each V chunk read once, serves all 4 queries of the group ----
    float4 acc[QPT][2];
    #pragma unroll
    for (int qi = 0; qi < QPT; ++qi) {
        acc[qi][0] = make_float4(0.f, 0.f, 0.f, 0.f);
        acc[qi][1] = make_float4(0.f, 0.f, 0.f, 0.f);
    }

    const int gb = lane & 24;   // group's base lane within the warp
    #pragma unroll
    for (int jj = 0; jj < NR; ++jj) {
        const float* vrow = v + gbase + (size_t)clampr(r0 - W + jj) * DM;
        const float4 v0 = *reinterpret_cast<const float4*>(vrow + ds * 4);
        const float4 v1 = *reinterpret_cast<const float4*>(vrow + 32 + ds * 4);
        #pragma unroll
        for (int qi = 0; qi < QPT; ++qi) {
            if (jj >= qi && jj <= qi + 2 * W) {
                // weight for (query r0+qi, row jj) lives in lane gb|qi, reg s[jj]
                const float x = __shfl_sync(0xffffffffu, s[jj], gb | qi);
                acc[qi][0].x = fmaf(x, v0.x, acc[qi][0].x);
                acc[qi][0].y = fmaf(x, v0.y, acc[qi][0].y);
                acc[qi][0].z = fmaf(x, v0.z, acc[qi][0].z);
                acc[qi][0].w = fmaf(x, v0.w, acc[qi][0].w);
                acc[qi][1].x = fmaf(x, v1.x, acc[qi][1].x);
                acc[qi][1].y = fmaf(x, v1.y, acc[qi][1].y);
                acc[qi][1].z = fmaf(x, v1.z, acc[qi][1].z);
                acc[qi][1].w = fmaf(x, v1.w, acc[qi][1].w);
            }
        }
    }

    #pragma unroll
    for (int qi = 0; qi < QPT; ++qi) {
        float* orow = out + gbase + (size_t)(r0 + qi) * DM;
        *reinterpret_cast<float4*>(orow + ds * 4)      = acc[qi][0];
        *reinterpret_cast<float4*>(orow + 32 + ds * 4) = acc[qi][1];
    }
}

extern "C" void kernel_launch(void* const* d_in, const int* in_sizes, int n_in,
                              void* d_out, int out_size) {
    const float* q = (const float*)d_in[0];
    const float* k = (const float*)d_in[1];
    const float* v = (const float*)d_in[2];
    float* out = (float*)d_out;

    const int B = in_sizes[0] / (S * DM);  // 256

    dim3 grid(H, 2, B);
    banded_attn_kernel<<<grid, THREADS>>>(q, k, v, out);
}

// round 15
// speedup vs baseline: 1.0863x; 1.0863x over previous
#include <cuda_runtime.h>
#include <cuda_bf16.h>
#include <math_constants.h>

// Banded sparse attention: B=256, S=128, DM=1024, H=16, Dh=64, half-width W=4.
// Grid (H, 2, B): each block owns 64 consecutive queries of one (b,h) tile.
// 128 threads, NO shared memory. 8-lane group owns 4 adjacent queries; lane
// `ds` owns dim chunks {ds, ds+8} (16B each) -> every K/V/Q/out instruction
// covers contiguous 128B per group (4 L1 wavefronts/warp-instruction).
// __launch_bounds__(128, 5): regs ~96 = the measured MLP sweet spot (capping
// to 80 regs for 6 blocks REDUCED achieved HBM bandwidth - see R14).
// V rows are L2-prefetched before the score phase (zero register cost) so the
// V DRAM fetch overlaps the K/score phase in this latency-limited regime.

namespace {
constexpr int S   = 128;
constexpr int DM  = 1024;
constexpr int H   = 16;
constexpr int W   = 4;
constexpr int QPT = 4;              // queries per 8-lane group
constexpr int NR  = 2 * W + QPT;    // 12 band-union rows per group
constexpr int NW  = 2 * W + 1;      // 9 live score slots per query
constexpr float SCALE = 0.125f;
constexpr int THREADS = 128;        // 4 warps = 16 groups = 64 queries/block
}  // namespace

__device__ __forceinline__ int clampr(int r) { return min(max(r, 0), S - 1); }

__device__ __forceinline__ void pf_l2(const float* p) {
    asm volatile("prefetch.global.L2 [%0];" :: "l"(p));
}

__global__ __launch_bounds__(THREADS, 5)
void banded_attn_kernel(const float* __restrict__ q,
                        const float* __restrict__ k,
                        const float* __restrict__ v,
                        float* __restrict__ out) {
    const int h    = blockIdx.x;
    const int half = blockIdx.y;     // which 64-query half of the tile
    const int b    = blockIdx.z;
    const int tid  = threadIdx.x;
    const int lane = tid & 31;
    const int warp = tid >> 5;

    const int ds  = lane & 7;                          // dim slice 0..7
    const int grp = warp * 4 + (lane >> 3);            // group 0..15
    const int r0  = half * 64 + grp * QPT;             // first query of group

    const size_t gbase = (size_t)b * S * DM + (size_t)h * 64;

    // ---- L2 prefetch of this group's 12 V rows (both 128B lines each).
    // Lanes 0..7 cover rows 0..7; lanes 0..3 also cover rows 8..11.
    // Zero register cost; overlaps V DRAM fetch with the score phase.
    {
        const float* pv = v + gbase + (size_t)clampr(r0 - W + ds) * DM;
        pf_l2(pv); pf_l2(pv + 32);
        if (ds < 4) {
            const float* pv2 = v + gbase + (size_t)clampr(r0 - W + 8 + ds) * DM;
            pf_l2(pv2); pf_l2(pv2 + 32);
        }
    }

    // ---- Scores ----
    // Owner lane ds==qi (qi<4) keeps s2[jj-qi] = score of query r0+qi vs row
    // r0-W+jj (9 live slots, compile-time indices).
    float s2[NW];
    #pragma unroll
    for (int t = 0; t < NW; ++t) s2[t] = 0.0f;

    {
        // This lane's slices of the 4 Q rows (chunks ds and ds+8)
        float4 qr[QPT][2];
        #pragma unroll
        for (int qi = 0; qi < QPT; ++qi) {
            const float* qrow = q + gbase + (size_t)(r0 + qi) * DM;
            qr[qi][0] = *reinterpret_cast<const float4*>(qrow + ds * 4);
            qr[qi][1] = *reinterpret_cast<const float4*>(qrow + 32 + ds * 4);
        }

        #pragma unroll
        for (int jj = 0; jj < NR; ++jj) {
            const float* krow = k + gbase + (size_t)clampr(r0 - W + jj) * DM;
            const float4 k0 = *reinterpret_cast<const float4*>(krow + ds * 4);
            const float4 k1 = *reinterpret_cast<const float4*>(krow + 32 + ds * 4);
            #pragma unroll
            for (int qi = 0; qi < QPT; ++qi) {
                if (jj >= qi && jj <= qi + 2 * W) {       // live (qi,jj) only
                    float p = 0.0f;
                    p = fmaf(qr[qi][0].x, k0.x, p); p = fmaf(qr[qi][0].y, k0.y, p);
                    p = fmaf(qr[qi][0].z, k0.z, p); p = fmaf(qr[qi][0].w, k0.w, p);
                    p = fmaf(qr[qi][1].x, k1.x, p); p = fmaf(qr[qi][1].y, k1.y, p);
                    p = fmaf(qr[qi][1].z, k1.z, p); p = fmaf(qr[qi][1].w, k1.w, p);
                    // reduce over the 8 dim-slices of this group
                    p += __shfl_xor_sync(0xffffffffu, p, 1);
                    p += __shfl_xor_sync(0xffffffffu, p, 2);
                    p += __shfl_xor_sync(0xffffffffu, p, 4);
                    if (ds == qi) s2[jj - qi] = p;        // compile-time index
                }
            }
        }
    }

    // ---- Softmax (owner lanes ds<4 own query r0+ds; others compute garbage
    //      that is never read) ----
    {
        float m = -CUDART_INF_F;
        #pragma unroll
        for (int t = 0; t < NW; ++t) {
            const int r = r0 - W + ds + t;               // key row for slot t
            const bool live = (r >= 0) && (r < S);
            s2[t] = live ? s2[t] * SCALE : -CUDART_INF_F;
            m = fmaxf(m, s2[t]);
        }
        float sum = 0.0f;
        #pragma unroll
        for (int t = 0; t < NW; ++t) { s2[t] = __expf(s2[t] - m); sum += s2[t]; }
        const float inv = 1.0f / sum;
        #pragma unroll
        for (int t = 0; t < NW; ++t) s2[t] *= inv;       // masked slots -> 0
    }

    // ---- Output: each V chunk read once, serves all 4 queries of the group ----
    float4 acc[QPT][2];
    #pragma unroll
    for (int qi = 0; qi < QPT; ++qi) {
        acc[qi][0] = make_float4(0.f, 0.f, 0.f, 0.f);
        acc[qi][1] = make_float4(0.f, 0.f, 0.f, 0.f);
    }

    const int gb = lane & 24;   // group's base lane within the warp
    #pragma unroll
    for (int jj = 0; jj < NR; ++jj) {
        const float* vrow = v + gbase + (size_t)clampr(r0 - W + jj) * DM;
        const float4 v0 = *reinterpret_cast<const float4*>(vrow + ds * 4);
        const float4 v1 = *reinterpret_cast<const float4*>(vrow + 32 + ds * 4);
        #pragma unroll
        for (int qi = 0; qi < QPT; ++qi) {
            if (jj >= qi && jj <= qi + 2 * W) {
                // weight for (query r0+qi, row jj): lane gb|qi, slot jj-qi
                const float x = __shfl_sync(0xffffffffu, s2[jj - qi], gb | qi);
                acc[qi][0].x = fmaf(x, v0.x, acc[qi][0].x);
                acc[qi][0].y = fmaf(x, v0.y, acc[qi][0].y);
                acc[qi][0].z = fmaf(x, v0.z, acc[qi][0].z);
                acc[qi][0].w = fmaf(x, v0.w, acc[qi][0].w);
                acc[qi][1].x = fmaf(x, v1.x, acc[qi][1].x);
                acc[qi][1].y = fmaf(x, v1.y, acc[qi][1].y);
                acc[qi][1].z = fmaf(x, v1.z, acc[qi][1].z);
                acc[qi][1].w = fmaf(x, v1.w, acc[qi][1].w);
            }
        }
    }

    #pragma unroll
    for (int qi = 0; qi < QPT; ++qi) {
        float* orow = out + gbase + (size_t)(r0 + qi) * DM;
        *reinterpret_cast<float4*>(orow + ds * 4)      = acc[qi][0];
        *reinterpret_cast<float4*>(orow + 32 + ds * 4) = acc[qi][1];
    }
}

extern "C" void kernel_launch(void* const* d_in, const int* in_sizes, int n_in,
                              void* d_out, int out_size) {
    const float* q = (const float*)d_in[0];
    const float* k = (const float*)d_in[1];
    const float* v = (const float*)d_in[2];
    float* out = (float*)d_out;

    const int B = in_sizes[0] / (S * DM);  // 256

    dim3 grid(H, 2, B);
    banded_attn_kernel<<<grid, THREADS>>>(q, k, v, out);
}